// round 2
// baseline (speedup 1.0000x reference)
#include <cuda_runtime.h>
#include <cuda_bf16.h>
#include <cstdint>

// Problem constants
#define B_   128
#define F_   1024
#define W_   32
#define H_   64
#define G4   256     // 4*H

// GEMM tiling: M=4096 (m = b*32 + t), N=256, K=1024
#define BM 128
#define BN 64
#define BK 32
#define PAD 40      // row stride in bf16 elems (80B, 16B-multiple, conflict-free)

// Scratch: gate pre-activations (input path, loop-invariant)
__device__ float g_G[B_ * W_ * G4];   // 4 MB

// ---------------------------------------------------------------------------
// Kernel 1: G = x^T-slices @ Wx + b, via bf16 tensor cores with hi/lo split
// (3-pass compensation: Ah*Bh + Al*Bh + Ah*Bl  -> ~fp32 accuracy).
// Grid (32, 4) = 128 CTAs, 256 threads (8 warps, each 32x32 of the 128x64 tile)
// ---------------------------------------------------------------------------
__device__ __forceinline__ void mma_bf16(float& d0, float& d1, float& d2, float& d3,
                                         uint32_t a0, uint32_t a1, uint32_t a2, uint32_t a3,
                                         uint32_t b0, uint32_t b1) {
    asm volatile(
        "mma.sync.aligned.m16n8k16.row.col.f32.bf16.bf16.f32 "
        "{%0,%1,%2,%3}, {%4,%5,%6,%7}, {%8,%9}, {%0,%1,%2,%3};\n"
        : "+f"(d0), "+f"(d1), "+f"(d2), "+f"(d3)
        : "r"(a0), "r"(a1), "r"(a2), "r"(a3), "r"(b0), "r"(b1));
}

__device__ __forceinline__ uint32_t lds_u32(const __nv_bfloat16* p) {
    return *reinterpret_cast<const uint32_t*>(p);
}

__global__ __launch_bounds__(256)
void gate_gemm_bf16(const float* __restrict__ x,
                    const float* __restrict__ Wx,
                    const float* __restrict__ bl) {
    __shared__ __nv_bfloat16 Ah[BM][PAD];
    __shared__ __nv_bfloat16 Al[BM][PAD];
    __shared__ __nv_bfloat16 Bh[BN][PAD];
    __shared__ __nv_bfloat16 Bl[BN][PAD];

    const int tid  = threadIdx.x;
    const int bm   = blockIdx.x;            // 0..31 m-tile
    const int bn   = blockIdx.y;            // 0..3  n-tile
    const int lane = tid & 31;
    const int warp = tid >> 5;
    const int wm   = (warp >> 1) * 32;      // warp m offset in tile
    const int wn   = (warp & 1) * 32;       // warp n offset in tile
    const int g    = lane >> 2;             // groupID
    const int tq   = lane & 3;              // threadID in group

    // ---- staging thread mappings ----
    // x tile: 128(m) x 32(k) fp32; 1024 float4 loads (float4 spans 4 t's = 4 m's)
    //   idx = i*256 + tid, i=0..3:  kk = idx>>5, q = idx&31, mm0 = q*4
    // W tile: 32(k) x 64(n) fp32; 512 float4 loads (float4 spans 4 n's)
    //   idx = i*256 + tid, i=0..1:  kk = idx>>4, n0 = (idx&15)*4
    int a_kk[4], a_mm0[4];
    const float* a_gp[4];
#pragma unroll
    for (int i = 0; i < 4; i++) {
        int idx = i * 256 + tid;
        a_kk[i]  = idx >> 5;
        int q    = idx & 31;
        a_mm0[i] = q * 4;
        int bloc = a_mm0[i] >> 5;           // batch within m-tile (0..3)
        int t0   = a_mm0[i] & 31;
        a_gp[i]  = x + (size_t)(bm * 4 + bloc) * (F_ * W_) + a_kk[i] * W_ + t0;
    }
    int w_kk[2], w_n0[2];
    const float* w_gp[2];
#pragma unroll
    for (int i = 0; i < 2; i++) {
        int idx = i * 256 + tid;
        w_kk[i] = idx >> 4;
        w_n0[i] = (idx & 15) * 4;
        w_gp[i] = Wx + (size_t)w_kk[i] * G4 + bn * 64 + w_n0[i];
    }

    float acc[2][4][4];                     // [m16 tile][n8 tile][c-regs]
#pragma unroll
    for (int mt = 0; mt < 2; mt++)
#pragma unroll
        for (int nt = 0; nt < 4; nt++)
#pragma unroll
            for (int r = 0; r < 4; r++) acc[mt][nt][r] = 0.f;

    // Prefetch k-tile 0 into registers
    float4 xr[4], wr[2];
#pragma unroll
    for (int i = 0; i < 4; i++) xr[i] = *reinterpret_cast<const float4*>(a_gp[i]);
#pragma unroll
    for (int i = 0; i < 2; i++) wr[i] = *reinterpret_cast<const float4*>(w_gp[i]);

    for (int kt = 0; kt < F_ / BK; kt++) {
        // ---- convert + stage current tile ----
#pragma unroll
        for (int i = 0; i < 4; i++) {
            const float* v = &xr[i].x;
#pragma unroll
            for (int j = 0; j < 4; j++) {
                float f = v[j];
                __nv_bfloat16 hi = __float2bfloat16(f);
                __nv_bfloat16 lo = __float2bfloat16(f - __bfloat162float(hi));
                Ah[a_mm0[i] + j][a_kk[i]] = hi;
                Al[a_mm0[i] + j][a_kk[i]] = lo;
            }
        }
#pragma unroll
        for (int i = 0; i < 2; i++) {
            const float* v = &wr[i].x;
#pragma unroll
            for (int j = 0; j < 4; j++) {
                float f = v[j];
                __nv_bfloat16 hi = __float2bfloat16(f);
                __nv_bfloat16 lo = __float2bfloat16(f - __bfloat162float(hi));
                Bh[w_n0[i] + j][w_kk[i]] = hi;
                Bl[w_n0[i] + j][w_kk[i]] = lo;
            }
        }
        __syncthreads();

        // ---- prefetch next k-tile (global latency hidden under MMAs) ----
        if (kt < F_ / BK - 1) {
#pragma unroll
            for (int i = 0; i < 4; i++)
                xr[i] = *reinterpret_cast<const float4*>(a_gp[i] + (size_t)(kt + 1) * BK * W_);
#pragma unroll
            for (int i = 0; i < 2; i++)
                wr[i] = *reinterpret_cast<const float4*>(w_gp[i] + (size_t)(kt + 1) * BK * G4);
        }

        // ---- tensor compute: 2 k16 sub-steps x 3 passes ----
#pragma unroll
        for (int ks = 0; ks < BK; ks += 16) {
            uint32_t ah[2][4], al[2][4];
#pragma unroll
            for (int mt = 0; mt < 2; mt++) {
                const __nv_bfloat16* ph = &Ah[wm + mt * 16 + g][ks + 2 * tq];
                const __nv_bfloat16* pl = &Al[wm + mt * 16 + g][ks + 2 * tq];
                ah[mt][0] = lds_u32(ph);
                ah[mt][1] = lds_u32(ph + 8 * PAD);
                ah[mt][2] = lds_u32(ph + 8);
                ah[mt][3] = lds_u32(ph + 8 * PAD + 8);
                al[mt][0] = lds_u32(pl);
                al[mt][1] = lds_u32(pl + 8 * PAD);
                al[mt][2] = lds_u32(pl + 8);
                al[mt][3] = lds_u32(pl + 8 * PAD + 8);
            }
            uint32_t bh[4][2], blo[4][2];
#pragma unroll
            for (int nt = 0; nt < 4; nt++) {
                const __nv_bfloat16* ph = &Bh[wn + nt * 8 + g][ks + 2 * tq];
                const __nv_bfloat16* pl = &Bl[wn + nt * 8 + g][ks + 2 * tq];
                bh[nt][0]  = lds_u32(ph);
                bh[nt][1]  = lds_u32(ph + 8);
                blo[nt][0] = lds_u32(pl);
                blo[nt][1] = lds_u32(pl + 8);
            }
#pragma unroll
            for (int mt = 0; mt < 2; mt++)
#pragma unroll
                for (int nt = 0; nt < 4; nt++) {
                    float* c = acc[mt][nt];
                    mma_bf16(c[0], c[1], c[2], c[3],
                             ah[mt][0], ah[mt][1], ah[mt][2], ah[mt][3],
                             bh[nt][0], bh[nt][1]);
                    mma_bf16(c[0], c[1], c[2], c[3],
                             al[mt][0], al[mt][1], al[mt][2], al[mt][3],
                             bh[nt][0], bh[nt][1]);
                    mma_bf16(c[0], c[1], c[2], c[3],
                             ah[mt][0], ah[mt][1], ah[mt][2], ah[mt][3],
                             blo[nt][0], blo[nt][1]);
                }
        }
        __syncthreads();
    }

    // ---- epilogue: bias + store ----
#pragma unroll
    for (int nt = 0; nt < 4; nt++) {
        int n = bn * 64 + wn + nt * 8 + 2 * tq;
        float2 bias = *reinterpret_cast<const float2*>(&bl[n]);
#pragma unroll
        for (int mt = 0; mt < 2; mt++) {
            int m = bm * 128 + wm + mt * 16 + g;
            float2 o0, o1;
            o0.x = acc[mt][nt][0] + bias.x;
            o0.y = acc[mt][nt][1] + bias.y;
            o1.x = acc[mt][nt][2] + bias.x;
            o1.y = acc[mt][nt][3] + bias.y;
            *reinterpret_cast<float2*>(&g_G[(size_t)m * G4 + n])       = o0;
            *reinterpret_cast<float2*>(&g_G[(size_t)(m + 8) * G4 + n]) = o1;
        }
    }
}

// ---------------------------------------------------------------------------
// Kernel 2: per-batch LSTM recurrence. One CTA per batch (128 CTAs),
// 256 threads = one per gate column. 4 accumulators break the FMA RAW chain;
// fast tanh via MUFU ex2. out[b,t,:] = cell state (reference appends c).
// ---------------------------------------------------------------------------
__device__ __forceinline__ float sigmoidf_(float v) {
    return 1.0f / (1.0f + __expf(-v));
}
__device__ __forceinline__ float tanhf_(float v) {
    v = fminf(fmaxf(v, -15.0f), 15.0f);
    float e = __expf(2.0f * v);
    return (e - 1.0f) / (e + 1.0f);
}

__global__ __launch_bounds__(256)
void lstm_rec(const float* __restrict__ Wh, float* __restrict__ out) {
    const int b = blockIdx.x;
    const int gi = threadIdx.x;    // gate column 0..255

    __shared__ float h_s[H_];
    __shared__ float gs[G4];

    // Wh[:, gi] in registers (coalesced row reads)
    float wh[H_];
#pragma unroll
    for (int k = 0; k < H_; k++) wh[k] = Wh[k * G4 + gi];

    if (gi < H_) h_s[gi] = 0.0f;
    float c = 0.0f;

    const float* Gb = g_G + (size_t)b * W_ * G4;
    float gv = Gb[gi];                       // prefetch t=0
    __syncthreads();

    for (int t = 0; t < W_; t++) {
        float a0 = gv, a1 = 0.f, a2 = 0.f, a3 = 0.f;
        if (t < W_ - 1) gv = Gb[(t + 1) * G4 + gi];

#pragma unroll
        for (int k = 0; k < H_ / 4; k++) {
            float4 h4 = *reinterpret_cast<const float4*>(&h_s[4 * k]);
            a0 = fmaf(h4.x, wh[4 * k + 0], a0);
            a1 = fmaf(h4.y, wh[4 * k + 1], a1);
            a2 = fmaf(h4.z, wh[4 * k + 2], a2);
            a3 = fmaf(h4.w, wh[4 * k + 3], a3);
        }
        gs[gi] = (a0 + a1) + (a2 + a3);
        __syncthreads();

        if (gi < H_) {
            float ig = sigmoidf_(gs[gi]);
            float fg = sigmoidf_(gs[H_ + gi]);
            float gg = tanhf_(gs[2 * H_ + gi]);
            float og = sigmoidf_(gs[3 * H_ + gi]);
            c = fg * c + ig * gg;
            float hn = og * tanhf_(c);
            out[(size_t)b * (W_ * H_) + t * H_ + gi] = c;   // output = cell state
            h_s[gi] = hn;
        }
        __syncthreads();
    }
}

// ---------------------------------------------------------------------------
// Launch
// ---------------------------------------------------------------------------
extern "C" void kernel_launch(void* const* d_in, const int* in_sizes, int n_in,
                              void* d_out, int out_size) {
    const float* x   = (const float*)d_in[0];   // [B, F, W]
    // d_in[1..5] (attention params) are mathematically dead: softmax over a
    // size-1 axis is identically 1, so x_tilde == x_t.
    const float* Wx  = (const float*)d_in[6];   // [F, 4H]
    const float* Wh  = (const float*)d_in[7];   // [H, 4H]
    const float* blm = (const float*)d_in[8];   // [4H]
    float* out = (float*)d_out;                 // [B, W, H]

    dim3 gg(32, 4);
    gate_gemm_bf16<<<gg, 256>>>(x, Wx, blm);
    lstm_rec<<<B_, 256>>>(Wh, out);
}

// round 6
// speedup vs baseline: 1.0288x; 1.0288x over previous
#include <cuda_runtime.h>
#include <cuda_bf16.h>
#include <cstdint>

// ---------------------------------------------------------------------------
// Problem: B=128, F=1024, W=32, H=64.  softmax over a size-1 axis == 1, so the
// attention branch is dead; model = plain LSTM over W steps, output = CELL
// state per step.
//   G[m][n] = sum_k x[b][k][t] * Wx[k][n] + b_lstm[n],  m = b*32 + t
//   then per-batch recurrence over t.
// GEMM runs on packed fp32 FFMA2 (fma.rn.f32x2): 2 MACs/issue, 2x plain FFMA.
// ---------------------------------------------------------------------------
#define B_   128
#define F_   1024
#define W_   32
#define H_   64
#define G4   256
#define BKP  36          // padded smem row stride (floats): 144B, 16B-aligned

// Scratch: gate pre-activations from the input path
__device__ float g_G[B_ * W_ * G4];   // 4 MB

// ---- packed fp32 helpers ---------------------------------------------------
__device__ __forceinline__ unsigned long long fma2_(unsigned long long a,
                                                    unsigned long long b,
                                                    unsigned long long c) {
    unsigned long long d;
    asm("fma.rn.f32x2 %0, %1, %2, %3;" : "=l"(d) : "l"(a), "l"(b), "l"(c));
    return d;
}
__device__ __forceinline__ unsigned long long pk2(float lo, float hi) {
    unsigned long long r;
    asm("mov.b64 %0, {%1, %2};" : "=l"(r) : "f"(lo), "f"(hi));
    return r;
}
__device__ __forceinline__ void upk2(float& lo, float& hi, unsigned long long v) {
    asm("mov.b64 {%0, %1}, %2;" : "=f"(lo), "=f"(hi) : "l"(v));
}

// ---------------------------------------------------------------------------
// Kernel 1: G = A @ Wx + b via FFMA2, accumulators packed along K.
// M=4096, N=256, K=1024. BM=128, BN=64, BK=32. Grid (32,4), 256 threads.
// Thread microtile 8(m) x 4(n); acc2[i][j] = {sum over even k, sum over odd k}.
// ---------------------------------------------------------------------------
__global__ __launch_bounds__(256, 1)
void gate_gemm_f2(const float* __restrict__ x,
                  const float* __restrict__ Wx,
                  const float* __restrict__ bl) {
    extern __shared__ float ds[];
    float* As = ds;                    // [2][128][BKP]
    float* Bs = ds + 2 * 128 * BKP;    // [2][64][BKP]

    const int tid = threadIdx.x;
    const int ty  = tid >> 4;          // 0..15 -> m rows ty*8..+7
    const int tx  = tid & 15;          // 0..15 -> n cols tx*4..+3
    const int m0  = blockIdx.x * 128;
    const int n0  = blockIdx.y * 64;

    // A staging: 128x32 floats, 16 per thread. m fixed per thread, k = kA0+2i.
    const int mA  = tid & 127;
    const int kA0 = tid >> 7;                       // 0 or 1
    const int bA  = (m0 + mA) >> 5;
    const int tA  = mA & 31;
    const float* xA = x + (size_t)bA * (F_ * W_) + tA;

    // B staging: 64x32 floats, 8 per thread. n fixed, k = kB0+4i.
    const int nB  = tid & 63;
    const int kB0 = tid >> 6;                       // 0..3
    const float* wB = Wx + n0 + nB;

    unsigned long long acc[8][4];
#pragma unroll
    for (int i = 0; i < 8; i++)
#pragma unroll
        for (int j = 0; j < 4; j++) acc[i][j] = 0ull;

    float ra[16], rb[8];
    // prefetch tile 0
#pragma unroll
    for (int i = 0; i < 16; i++) ra[i] = xA[(size_t)(kA0 + 2 * i) * W_];
#pragma unroll
    for (int i = 0; i < 8; i++)  rb[i] = wB[(size_t)(kB0 + 4 * i) * G4];

    int buf = 0;
    for (int kt = 0; kt < F_ / 32; kt++) {
        // stage
        float* Ab = As + buf * (128 * BKP);
        float* Bb = Bs + buf * (64 * BKP);
#pragma unroll
        for (int i = 0; i < 16; i++) Ab[mA * BKP + kA0 + 2 * i] = ra[i];
#pragma unroll
        for (int i = 0; i < 8; i++)  Bb[nB * BKP + kB0 + 4 * i] = rb[i];
        __syncthreads();

        // prefetch next tile into regs
        if (kt < F_ / 32 - 1) {
            const float* xN = xA + (size_t)(kt + 1) * 32 * W_;
            const float* wN = wB + (size_t)(kt + 1) * 32 * G4;
#pragma unroll
            for (int i = 0; i < 16; i++) ra[i] = xN[(size_t)(kA0 + 2 * i) * W_];
#pragma unroll
            for (int i = 0; i < 8; i++)  rb[i] = wN[(size_t)(kB0 + 4 * i) * G4];
        }

        // compute: 8 groups of 4 k's
        const float* Ar = Ab + ty * 8 * BKP;
        const float* Br = Bb + tx * 4 * BKP;
#pragma unroll
        for (int kq = 0; kq < 8; kq++) {
            ulonglong2 av[8], bv[4];
#pragma unroll
            for (int i = 0; i < 8; i++)
                av[i] = *reinterpret_cast<const ulonglong2*>(Ar + i * BKP + 4 * kq);
#pragma unroll
            for (int j = 0; j < 4; j++)
                bv[j] = *reinterpret_cast<const ulonglong2*>(Br + j * BKP + 4 * kq);
#pragma unroll
            for (int i = 0; i < 8; i++)
#pragma unroll
                for (int j = 0; j < 4; j++) {
                    acc[i][j] = fma2_(av[i].x, bv[j].x, acc[i][j]);
                    acc[i][j] = fma2_(av[i].y, bv[j].y, acc[i][j]);
                }
        }
        buf ^= 1;
        __syncthreads();
    }

    // epilogue: horizontal add + bias, vectorized store
    float4 bias = *reinterpret_cast<const float4*>(&bl[n0 + tx * 4]);
#pragma unroll
    for (int i = 0; i < 8; i++) {
        int m = m0 + ty * 8 + i;
        float lo, hi;
        float4 o;
        upk2(lo, hi, acc[i][0]); o.x = lo + hi + bias.x;
        upk2(lo, hi, acc[i][1]); o.y = lo + hi + bias.y;
        upk2(lo, hi, acc[i][2]); o.z = lo + hi + bias.z;
        upk2(lo, hi, acc[i][3]); o.w = lo + hi + bias.w;
        *reinterpret_cast<float4*>(&g_G[(size_t)m * G4 + n0 + tx * 4]) = o;
    }
}

// ---------------------------------------------------------------------------
// Kernel 2: LSTM recurrence. 1 CTA per batch, 256 threads = 8 warps.
// Warp w owns hidden units 8w..8w+7. Lane l computes the FULL 64-length dot
// for (gate = l>>3, unit = 8w + (l&7)); gates gathered by 3 warp shuffles
// (no smem round-trip); h double-buffered -> ONE __syncthreads per step.
// ---------------------------------------------------------------------------
__device__ __forceinline__ float sig_(float v) {
    return 1.0f / (1.0f + __expf(-v));
}
__device__ __forceinline__ float th_(float v) {
    v = fminf(fmaxf(v, -15.0f), 15.0f);
    float e = __expf(2.0f * v);
    return 1.0f - 2.0f / (e + 1.0f);
}

__global__ __launch_bounds__(256)
void lstm_rec(const float* __restrict__ Wh, float* __restrict__ out) {
    const int b   = blockIdx.x;
    const int tid = threadIdx.x;
    const int w   = tid >> 5;
    const int l   = tid & 31;
    const int u   = 8 * w + (l & 7);   // hidden unit
    const int gq  = l >> 3;            // gate index 0..3 (i,f,g,o)
    const int n   = gq * 64 + u;       // column in [4H]

    __shared__ __align__(16) float hbuf[2][H_];

    // Wh[:, n] packed along k (64 weights -> 32 f32x2)
    unsigned long long wh2[32];
#pragma unroll
    for (int kk = 0; kk < 32; kk++)
        wh2[kk] = pk2(Wh[(2 * kk) * G4 + n], Wh[(2 * kk + 1) * G4 + n]);

    if (tid < H_) hbuf[0][tid] = 0.0f;
    float c = 0.0f;

    const float* Gb = g_G + (size_t)b * W_ * G4;
    float gv = Gb[n];                  // prefetch t = 0
    __syncthreads();

    int p = 0;
    for (int t = 0; t < W_; t++) {
        const unsigned long long* h2 =
            reinterpret_cast<const unsigned long long*>(hbuf[p]);

        unsigned long long a0 = pk2(gv, 0.0f), a1 = 0ull, a2 = 0ull, a3 = 0ull;
        if (t < W_ - 1) gv = Gb[(size_t)(t + 1) * G4 + n];

#pragma unroll
        for (int kk = 0; kk < 8; kk++) {
            a0 = fma2_(h2[kk],      wh2[kk],      a0);
            a1 = fma2_(h2[8 + kk],  wh2[8 + kk],  a1);
            a2 = fma2_(h2[16 + kk], wh2[16 + kk], a2);
            a3 = fma2_(h2[24 + kk], wh2[24 + kk], a3);
        }
        float s0, s1, s2, s3, s4, s5, s6, s7;
        upk2(s0, s1, a0); upk2(s2, s3, a1);
        upk2(s4, s5, a2); upk2(s6, s7, a3);
        float v = ((s0 + s1) + (s2 + s3)) + ((s4 + s5) + (s6 + s7));

        // gather the 4 gate values of unit (l&7) from lanes {0,8,16,24}+(l&7)
        int src = l & 7;
        float g0 = __shfl_sync(0xFFFFFFFFu, v, src);
        float g1 = __shfl_sync(0xFFFFFFFFu, v, src + 8);
        float g2 = __shfl_sync(0xFFFFFFFFu, v, src + 16);
        float g3 = __shfl_sync(0xFFFFFFFFu, v, src + 24);

        if (l < 8) {
            float ig = sig_(g0);
            float fg = sig_(g1);
            float gg = th_(g2);
            float og = sig_(g3);
            c = fg * c + ig * gg;
            out[(size_t)b * (W_ * H_) + t * H_ + u] = c;  // output = cell state
            hbuf[p ^ 1][u] = og * th_(c);
        }
        p ^= 1;
        __syncthreads();
    }
}

// ---------------------------------------------------------------------------
// Launch
// ---------------------------------------------------------------------------
#define GEMM_SMEM ((2 * 128 * BKP + 2 * 64 * BKP) * 4)

extern "C" void kernel_launch(void* const* d_in, const int* in_sizes, int n_in,
                              void* d_out, int out_size) {
    const float* x   = (const float*)d_in[0];   // [B, F, W]
    // d_in[1..5] (attention params) are dead: softmax over size-1 axis == 1.
    const float* Wx  = (const float*)d_in[6];   // [F, 4H]
    const float* Wh  = (const float*)d_in[7];   // [H, 4H]
    const float* blm = (const float*)d_in[8];   // [4H]
    float* out = (float*)d_out;                 // [B, W, H]

    cudaFuncSetAttribute(gate_gemm_f2,
                         cudaFuncAttributeMaxDynamicSharedMemorySize, GEMM_SMEM);

    gate_gemm_f2<<<dim3(32, 4), 256, GEMM_SMEM>>>(x, Wx, blm);
    lstm_rec<<<B_, 256>>>(Wh, out);
}

// round 7
// speedup vs baseline: 1.9088x; 1.8554x over previous
#include <cuda_runtime.h>
#include <cuda_bf16.h>
#include <cstdint>

// ---------------------------------------------------------------------------
// Problem: B=128, F=1024, W=32, H=64.  softmax over a size-1 axis == 1, so the
// attention branch is dead; model = plain LSTM, output = CELL state per step.
//   G[m][n] = sum_k x[b][k][t] * Wx[k][n] + b_lstm[n],  m = b*32 + t
// GEMM: bf16 mma.sync with hi/lo 3-pass compensation (rel_err ~1e-5 proven).
// ---------------------------------------------------------------------------
#define B_   128
#define F_   1024
#define W_   32
#define H_   64
#define G4   256
#define PADK 40                  // smem row stride in bf16 (80B, conflict-free)

__device__ float          g_G [B_ * W_ * G4];    // gate preactivations, 4 MB
__device__ __nv_bfloat16  g_xh[B_ * W_ * F_];    // x^T hi  [m][k], 8 MB
__device__ __nv_bfloat16  g_xl[B_ * W_ * F_];    // x^T lo
__device__ __nv_bfloat16  g_wh[G4 * F_];         // Wx^T hi [n][k], 512 KB
__device__ __nv_bfloat16  g_wl[G4 * F_];         // Wx^T lo

// ---- helpers ---------------------------------------------------------------
__device__ __forceinline__ void split2(float a, float b, uint32_t& hi, uint32_t& lo) {
    uint32_t ua = __float_as_uint(a), ub = __float_as_uint(b);
    hi = (ua >> 16) | (ub & 0xFFFF0000u);                   // truncated bf16 pair
    float la = a - __uint_as_float(ua & 0xFFFF0000u);
    float lb = b - __uint_as_float(ub & 0xFFFF0000u);
    __nv_bfloat162 p = __floats2bfloat162_rn(la, lb);
    lo = *reinterpret_cast<uint32_t*>(&p);
}
__device__ __forceinline__ void mma_bf16(float* c,
                                         uint32_t a0, uint32_t a1, uint32_t a2, uint32_t a3,
                                         uint32_t b0, uint32_t b1) {
    asm volatile(
        "mma.sync.aligned.m16n8k16.row.col.f32.bf16.bf16.f32 "
        "{%0,%1,%2,%3}, {%4,%5,%6,%7}, {%8,%9}, {%0,%1,%2,%3};\n"
        : "+f"(c[0]), "+f"(c[1]), "+f"(c[2]), "+f"(c[3])
        : "r"(a0), "r"(a1), "r"(a2), "r"(a3), "r"(b0), "r"(b1));
}
__device__ __forceinline__ uint32_t lds32(const __nv_bfloat16* p) {
    return *reinterpret_cast<const uint32_t*>(p);
}

// ---------------------------------------------------------------------------
// Kernel 0a: x [B][F][W] -> g_xh/g_xl [m=b*32+t][k=f]  (transpose + split)
// ---------------------------------------------------------------------------
__global__ __launch_bounds__(256) void split_x(const float* __restrict__ x) {
    __shared__ float tile[128][33];
    const int tid = threadIdx.x;
    const int b   = blockIdx.y;
    const int f0  = blockIdx.x * 128;
#pragma unroll
    for (int i = 0; i < 4; i++) {
        int idx = i * 256 + tid;
        int f = idx >> 3, tq = idx & 7;
        float4 v = *reinterpret_cast<const float4*>(x + ((size_t)b * F_ + f0 + f) * W_ + tq * 4);
        tile[f][tq * 4 + 0] = v.x; tile[f][tq * 4 + 1] = v.y;
        tile[f][tq * 4 + 2] = v.z; tile[f][tq * 4 + 3] = v.w;
    }
    __syncthreads();
    const int t  = tid >> 3;
    const int fo = (tid & 7) * 16;
    uint32_t hi[8], lo[8];
#pragma unroll
    for (int p = 0; p < 8; p++)
        split2(tile[fo + 2 * p][t], tile[fo + 2 * p + 1][t], hi[p], lo[p]);
    size_t dst = ((size_t)b * W_ + t) * F_ + f0 + fo;
    *reinterpret_cast<uint4*>(g_xh + dst)     = make_uint4(hi[0], hi[1], hi[2], hi[3]);
    *reinterpret_cast<uint4*>(g_xh + dst + 8) = make_uint4(hi[4], hi[5], hi[6], hi[7]);
    *reinterpret_cast<uint4*>(g_xl + dst)     = make_uint4(lo[0], lo[1], lo[2], lo[3]);
    *reinterpret_cast<uint4*>(g_xl + dst + 8) = make_uint4(lo[4], lo[5], lo[6], lo[7]);
}

// ---------------------------------------------------------------------------
// Kernel 0b: Wx [K][N] -> g_wh/g_wl [n][k]  (transpose + split)
// ---------------------------------------------------------------------------
__global__ __launch_bounds__(256) void split_w(const float* __restrict__ Wx) {
    __shared__ float tile[64][65];
    const int tid = threadIdx.x;
    const int k0  = blockIdx.x * 64;
    const int n0  = blockIdx.y * 64;
#pragma unroll
    for (int i = 0; i < 4; i++) {
        int idx = i * 256 + tid;
        int k = idx >> 4, nq = idx & 15;
        float4 v = *reinterpret_cast<const float4*>(Wx + (size_t)(k0 + k) * G4 + n0 + nq * 4);
        tile[k][nq * 4 + 0] = v.x; tile[k][nq * 4 + 1] = v.y;
        tile[k][nq * 4 + 2] = v.z; tile[k][nq * 4 + 3] = v.w;
    }
    __syncthreads();
    const int n  = tid >> 2;
    const int ko = (tid & 3) * 16;
    uint32_t hi[8], lo[8];
#pragma unroll
    for (int p = 0; p < 8; p++)
        split2(tile[ko + 2 * p][n], tile[ko + 2 * p + 1][n], hi[p], lo[p]);
    size_t dst = (size_t)(n0 + n) * F_ + k0 + ko;
    *reinterpret_cast<uint4*>(g_wh + dst)     = make_uint4(hi[0], hi[1], hi[2], hi[3]);
    *reinterpret_cast<uint4*>(g_wh + dst + 8) = make_uint4(hi[4], hi[5], hi[6], hi[7]);
    *reinterpret_cast<uint4*>(g_wl + dst)     = make_uint4(lo[0], lo[1], lo[2], lo[3]);
    *reinterpret_cast<uint4*>(g_wl + dst + 8) = make_uint4(lo[4], lo[5], lo[6], lo[7]);
}

// ---------------------------------------------------------------------------
// Kernel 1: mma.sync GEMM, 3-pass hi/lo. CTA tile 128x64, BK=32, grid (32,4),
// 256 threads = 8 warps (2m x 4n), warp tile m64 x n16. Double-buffered smem,
// one __syncthreads per k-tile. Staging = LDG.128 -> STS.128 (pre-split data).
// ---------------------------------------------------------------------------
#define AH_E  0
#define AL_E  (128 * PADK)
#define BH_E  (2 * 128 * PADK)
#define BL_E  (2 * 128 * PADK + 64 * PADK)
#define BUFE  (2 * 128 * PADK + 2 * 64 * PADK)      // 15360 bf16 = 30720 B
#define GEMM_SMEM (2 * BUFE * 2)                    // 61440 B

__global__ __launch_bounds__(256, 1)
void gate_gemm_mma(const float* __restrict__ bl) {
    extern __shared__ __nv_bfloat16 sm[];

    const int tid  = threadIdx.x;
    const int warp = tid >> 5;
    const int lane = tid & 31;
    const int wm   = (warp >> 2) * 64;      // 0 or 64
    const int wn   = (warp & 3) * 16;       // 0,16,32,48
    const int g    = lane >> 2;
    const int tq   = lane & 3;
    const int m0   = blockIdx.x * 128;
    const int n0   = blockIdx.y * 64;

    // staging maps
    const int arow0 = tid >> 2;             // A rows: i*64 + arow0? no: idx=i*256+tid
    const int av    = tid & 3;              // 16B vec within 64B row
    const int brow  = tid >> 2;             // B row 0..63
    // A: i=0 -> rows 0..63, i=1 -> rows 64..127 (row = i*64 + (tid>>2))
    const uint4* pxh0 = reinterpret_cast<const uint4*>(g_xh + (size_t)(m0 + arow0) * F_) + av;
    const uint4* pxh1 = reinterpret_cast<const uint4*>(g_xh + (size_t)(m0 + 64 + arow0) * F_) + av;
    const uint4* pxl0 = reinterpret_cast<const uint4*>(g_xl + (size_t)(m0 + arow0) * F_) + av;
    const uint4* pxl1 = reinterpret_cast<const uint4*>(g_xl + (size_t)(m0 + 64 + arow0) * F_) + av;
    const uint4* pwh  = reinterpret_cast<const uint4*>(g_wh + (size_t)(n0 + brow) * F_) + av;
    const uint4* pwl  = reinterpret_cast<const uint4*>(g_wl + (size_t)(n0 + brow) * F_) + av;
    // per k-tile advance: 32 bf16 = 64 B = 4 uint4

    float acc[4][2][4];
#pragma unroll
    for (int mt = 0; mt < 4; mt++)
#pragma unroll
        for (int nt = 0; nt < 2; nt++)
#pragma unroll
            for (int r = 0; r < 4; r++) acc[mt][nt][r] = 0.f;

    uint4 rh0, rh1, rl0, rl1, rbh, rbl;
    rh0 = pxh0[0]; rh1 = pxh1[0]; rl0 = pxl0[0]; rl1 = pxl1[0];
    rbh = pwh[0];  rbl = pwl[0];

    const int NKT = F_ / 32;                // 32 k-tiles
    for (int kt = 0; kt < NKT; kt++) {
        __nv_bfloat16* buf = sm + (kt & 1) * BUFE;
        // stage (STS.128)
        *reinterpret_cast<uint4*>(buf + AH_E + (size_t)arow0 * PADK + av * 8)        = rh0;
        *reinterpret_cast<uint4*>(buf + AH_E + (size_t)(64 + arow0) * PADK + av * 8) = rh1;
        *reinterpret_cast<uint4*>(buf + AL_E + (size_t)arow0 * PADK + av * 8)        = rl0;
        *reinterpret_cast<uint4*>(buf + AL_E + (size_t)(64 + arow0) * PADK + av * 8) = rl1;
        *reinterpret_cast<uint4*>(buf + BH_E + (size_t)brow * PADK + av * 8)         = rbh;
        *reinterpret_cast<uint4*>(buf + BL_E + (size_t)brow * PADK + av * 8)         = rbl;
        __syncthreads();

        // prefetch next k-tile
        if (kt < NKT - 1) {
            int o = (kt + 1) * 4;
            rh0 = pxh0[o]; rh1 = pxh1[o]; rl0 = pxl0[o]; rl1 = pxl1[o];
            rbh = pwh[o];  rbl = pwl[o];
        }

        // compute 2 x k16
#pragma unroll
        for (int ks = 0; ks < 32; ks += 16) {
            uint32_t bh[2][2], blo[2][2];
#pragma unroll
            for (int nt = 0; nt < 2; nt++) {
                const __nv_bfloat16* pb  = buf + BH_E + (size_t)(wn + nt * 8 + g) * PADK + ks + 2 * tq;
                const __nv_bfloat16* pbl = buf + BL_E + (size_t)(wn + nt * 8 + g) * PADK + ks + 2 * tq;
                bh[nt][0]  = lds32(pb);  bh[nt][1]  = lds32(pb + 8);
                blo[nt][0] = lds32(pbl); blo[nt][1] = lds32(pbl + 8);
            }
#pragma unroll
            for (int mt = 0; mt < 4; mt++) {
                const __nv_bfloat16* pa  = buf + AH_E + (size_t)(wm + mt * 16 + g) * PADK + ks + 2 * tq;
                const __nv_bfloat16* pal = buf + AL_E + (size_t)(wm + mt * 16 + g) * PADK + ks + 2 * tq;
                uint32_t a0 = lds32(pa),             a1 = lds32(pa + 8 * PADK);
                uint32_t a2 = lds32(pa + 8),         a3 = lds32(pa + 8 * PADK + 8);
                uint32_t l0 = lds32(pal),            l1 = lds32(pal + 8 * PADK);
                uint32_t l2 = lds32(pal + 8),        l3 = lds32(pal + 8 * PADK + 8);
#pragma unroll
                for (int nt = 0; nt < 2; nt++) {
                    mma_bf16(acc[mt][nt], a0, a1, a2, a3, bh[nt][0],  bh[nt][1]);
                    mma_bf16(acc[mt][nt], l0, l1, l2, l3, bh[nt][0],  bh[nt][1]);
                    mma_bf16(acc[mt][nt], a0, a1, a2, a3, blo[nt][0], blo[nt][1]);
                }
            }
        }
        // NOTE: single barrier per iter is safe with double buffering:
        // writes to buf^1 at iter k+1 happen after sync(k), which orders them
        // after all reads of buf^1 (last read at iter k-1).
    }

    // epilogue: bias + store (c0,c1 at row m, c2,c3 at m+8)
#pragma unroll
    for (int nt = 0; nt < 2; nt++) {
        int n = n0 + wn + nt * 8 + 2 * tq;
        float2 bias = *reinterpret_cast<const float2*>(&bl[n]);
#pragma unroll
        for (int mt = 0; mt < 4; mt++) {
            int m = m0 + wm + mt * 16 + g;
            float2 o0, o1;
            o0.x = acc[mt][nt][0] + bias.x;  o0.y = acc[mt][nt][1] + bias.y;
            o1.x = acc[mt][nt][2] + bias.x;  o1.y = acc[mt][nt][3] + bias.y;
            *reinterpret_cast<float2*>(&g_G[(size_t)m * G4 + n])       = o0;
            *reinterpret_cast<float2*>(&g_G[(size_t)(m + 8) * G4 + n]) = o1;
        }
    }
}

// ---------------------------------------------------------------------------
// Kernel 2: LSTM recurrence. 1 CTA/batch, 256 threads = 8 warps.
// Lane l of warp w: dot for (gate = l>>3, unit = 8w + (l&7)).
// G slice preloaded into 32 registers (no in-loop LDG); gates gathered by
// warp shuffles; h double-buffered -> ONE __syncthreads per step.
// ---------------------------------------------------------------------------
__device__ __forceinline__ unsigned long long pk2(float lo, float hi) {
    unsigned long long r;
    asm("mov.b64 %0, {%1, %2};" : "=l"(r) : "f"(lo), "f"(hi));
    return r;
}
__device__ __forceinline__ unsigned long long fma2_(unsigned long long a,
                                                    unsigned long long b,
                                                    unsigned long long c) {
    unsigned long long d;
    asm("fma.rn.f32x2 %0, %1, %2, %3;" : "=l"(d) : "l"(a), "l"(b), "l"(c));
    return d;
}
__device__ __forceinline__ void upk2(float& lo, float& hi, unsigned long long v) {
    asm("mov.b64 {%0, %1}, %2;" : "=f"(lo), "=f"(hi) : "l"(v));
}
__device__ __forceinline__ float sig_(float v) { return 1.0f / (1.0f + __expf(-v)); }
__device__ __forceinline__ float th_(float v) {
    v = fminf(fmaxf(v, -15.0f), 15.0f);
    float e = __expf(2.0f * v);
    return 1.0f - 2.0f / (e + 1.0f);
}

__global__ __launch_bounds__(256)
void lstm_rec(const float* __restrict__ Wh, float* __restrict__ out) {
    const int b   = blockIdx.x;
    const int tid = threadIdx.x;
    const int w   = tid >> 5;
    const int l   = tid & 31;
    const int u   = 8 * w + (l & 7);
    const int gq  = l >> 3;
    const int n   = gq * 64 + u;

    __shared__ __align__(16) float hbuf[2][H_];

    unsigned long long wh2[32];
#pragma unroll
    for (int kk = 0; kk < 32; kk++)
        wh2[kk] = pk2(Wh[(2 * kk) * G4 + n], Wh[(2 * kk + 1) * G4 + n]);

    // preload the full G slice for this column: 32 regs, no in-loop LDG
    const float* Gb = g_G + (size_t)b * W_ * G4;
    float gr[W_];
#pragma unroll
    for (int t = 0; t < W_; t++) gr[t] = Gb[(size_t)t * G4 + n];

    if (tid < H_) hbuf[0][tid] = 0.0f;
    float c = 0.0f;
    __syncthreads();

    int p = 0;
    for (int t = 0; t < W_; t++) {
        const unsigned long long* h2 =
            reinterpret_cast<const unsigned long long*>(hbuf[p]);

        unsigned long long a0 = pk2(gr[t], 0.0f), a1 = 0ull, a2 = 0ull, a3 = 0ull;
#pragma unroll
        for (int kk = 0; kk < 8; kk++) {
            a0 = fma2_(h2[kk],      wh2[kk],      a0);
            a1 = fma2_(h2[8 + kk],  wh2[8 + kk],  a1);
            a2 = fma2_(h2[16 + kk], wh2[16 + kk], a2);
            a3 = fma2_(h2[24 + kk], wh2[24 + kk], a3);
        }
        float s0, s1, s2, s3, s4, s5, s6, s7;
        upk2(s0, s1, a0); upk2(s2, s3, a1);
        upk2(s4, s5, a2); upk2(s6, s7, a3);
        float v = ((s0 + s1) + (s2 + s3)) + ((s4 + s5) + (s6 + s7));

        int src = l & 7;
        float g0 = __shfl_sync(0xFFFFFFFFu, v, src);
        float g1 = __shfl_sync(0xFFFFFFFFu, v, src + 8);
        float g2 = __shfl_sync(0xFFFFFFFFu, v, src + 16);
        float g3 = __shfl_sync(0xFFFFFFFFu, v, src + 24);

        // all lanes compute (predication doesn't reduce warp issue cost)
        float ig = sig_(g0);
        float fg = sig_(g1);
        float gg = th_(g2);
        float og = sig_(g3);
        c = fg * c + ig * gg;
        float hn = og * th_(c);
        if (l < 8) {
            out[(size_t)b * (W_ * H_) + t * H_ + u] = c;   // output = cell state
            hbuf[p ^ 1][u] = hn;
        }
        p ^= 1;
        __syncthreads();
    }
}

// ---------------------------------------------------------------------------
// Launch
// ---------------------------------------------------------------------------
extern "C" void kernel_launch(void* const* d_in, const int* in_sizes, int n_in,
                              void* d_out, int out_size) {
    const float* x   = (const float*)d_in[0];   // [B, F, W]
    // d_in[1..5] (attention params) are dead: softmax over size-1 axis == 1.
    const float* Wx  = (const float*)d_in[6];   // [F, 4H]
    const float* Wh  = (const float*)d_in[7];   // [H, 4H]
    const float* blm = (const float*)d_in[8];   // [4H]
    float* out = (float*)d_out;                 // [B, W, H]

    cudaFuncSetAttribute(gate_gemm_mma,
                         cudaFuncAttributeMaxDynamicSharedMemorySize, GEMM_SMEM);

    split_x<<<dim3(8, 128), 256>>>(x);
    split_w<<<dim3(16, 4), 256>>>(Wx);
    gate_gemm_mma<<<dim3(32, 4), 256, GEMM_SMEM>>>(blm);
    lstm_rec<<<B_, 256>>>(Wh, out);
}

// round 8
// speedup vs baseline: 2.4018x; 1.2583x over previous
#include <cuda_runtime.h>
#include <cuda_bf16.h>
#include <cstdint>

// ---------------------------------------------------------------------------
// Problem: B=128, F=1024, W=32, H=64.  softmax over a size-1 axis == 1, so the
// attention branch is dead; model = plain LSTM, output = CELL state per step.
//   G[m][n] = sum_k x[b][k][t] * Wx[k][n] + b_lstm[n],  m = b*32 + t
// GEMM: bf16 mma.sync with hi/lo 3-pass compensation (rel_err ~1.6e-5 proven).
// ---------------------------------------------------------------------------
#define B_   128
#define F_   1024
#define W_   32
#define H_   64
#define G4   256
#define PADK 40                  // smem row stride in bf16 (80B): conflict-free

__device__ float          g_G [B_ * W_ * G4];    // gate preactivations, 4 MB
__device__ __nv_bfloat16  g_xh[B_ * W_ * F_];    // x^T hi  [m][k], 8 MB
__device__ __nv_bfloat16  g_xl[B_ * W_ * F_];    // x^T lo
__device__ __nv_bfloat16  g_wh[G4 * F_];         // Wx^T hi [n][k], 512 KB
__device__ __nv_bfloat16  g_wl[G4 * F_];         // Wx^T lo

// ---- helpers ---------------------------------------------------------------
__device__ __forceinline__ uint32_t smaddr(const void* p) {
    return (uint32_t)__cvta_generic_to_shared(p);
}
__device__ __forceinline__ void split2(float a, float b, uint32_t& hi, uint32_t& lo) {
    uint32_t ua = __float_as_uint(a), ub = __float_as_uint(b);
    hi = (ua >> 16) | (ub & 0xFFFF0000u);                   // truncated bf16 pair
    float la = a - __uint_as_float(ua & 0xFFFF0000u);
    float lb = b - __uint_as_float(ub & 0xFFFF0000u);
    __nv_bfloat162 p = __floats2bfloat162_rn(la, lb);
    lo = *reinterpret_cast<uint32_t*>(&p);
}
__device__ __forceinline__ void mma_bf16(float* c,
                                         const uint32_t* a, uint32_t b0, uint32_t b1) {
    asm volatile(
        "mma.sync.aligned.m16n8k16.row.col.f32.bf16.bf16.f32 "
        "{%0,%1,%2,%3}, {%4,%5,%6,%7}, {%8,%9}, {%0,%1,%2,%3};\n"
        : "+f"(c[0]), "+f"(c[1]), "+f"(c[2]), "+f"(c[3])
        : "r"(a[0]), "r"(a[1]), "r"(a[2]), "r"(a[3]), "r"(b0), "r"(b1));
}
__device__ __forceinline__ void ldsm4(uint32_t* r, uint32_t addr) {
    asm volatile("ldmatrix.sync.aligned.m8n8.x4.shared.b16 {%0,%1,%2,%3}, [%4];"
                 : "=r"(r[0]), "=r"(r[1]), "=r"(r[2]), "=r"(r[3]) : "r"(addr));
}

// ---------------------------------------------------------------------------
// Kernel 0a: x [B][F][W] -> g_xh/g_xl [m=b*32+t][k=f]  (transpose + split)
// ---------------------------------------------------------------------------
__global__ __launch_bounds__(256) void split_x(const float* __restrict__ x) {
    __shared__ float tile[128][33];
    const int tid = threadIdx.x;
    const int b   = blockIdx.y;
    const int f0  = blockIdx.x * 128;
#pragma unroll
    for (int i = 0; i < 4; i++) {
        int idx = i * 256 + tid;
        int f = idx >> 3, tq = idx & 7;
        float4 v = *reinterpret_cast<const float4*>(x + ((size_t)b * F_ + f0 + f) * W_ + tq * 4);
        tile[f][tq * 4 + 0] = v.x; tile[f][tq * 4 + 1] = v.y;
        tile[f][tq * 4 + 2] = v.z; tile[f][tq * 4 + 3] = v.w;
    }
    __syncthreads();
    const int t  = tid >> 3;
    const int fo = (tid & 7) * 16;
    uint32_t hi[8], lo[8];
#pragma unroll
    for (int p = 0; p < 8; p++)
        split2(tile[fo + 2 * p][t], tile[fo + 2 * p + 1][t], hi[p], lo[p]);
    size_t dst = ((size_t)b * W_ + t) * F_ + f0 + fo;
    *reinterpret_cast<uint4*>(g_xh + dst)     = make_uint4(hi[0], hi[1], hi[2], hi[3]);
    *reinterpret_cast<uint4*>(g_xh + dst + 8) = make_uint4(hi[4], hi[5], hi[6], hi[7]);
    *reinterpret_cast<uint4*>(g_xl + dst)     = make_uint4(lo[0], lo[1], lo[2], lo[3]);
    *reinterpret_cast<uint4*>(g_xl + dst + 8) = make_uint4(lo[4], lo[5], lo[6], lo[7]);
}

// ---------------------------------------------------------------------------
// Kernel 0b: Wx [K][N] -> g_wh/g_wl [n][k]  (transpose + split)
// ---------------------------------------------------------------------------
__global__ __launch_bounds__(256) void split_w(const float* __restrict__ Wx) {
    __shared__ float tile[64][65];
    const int tid = threadIdx.x;
    const int k0  = blockIdx.x * 64;
    const int n0  = blockIdx.y * 64;
#pragma unroll
    for (int i = 0; i < 4; i++) {
        int idx = i * 256 + tid;
        int k = idx >> 4, nq = idx & 15;
        float4 v = *reinterpret_cast<const float4*>(Wx + (size_t)(k0 + k) * G4 + n0 + nq * 4);
        tile[k][nq * 4 + 0] = v.x; tile[k][nq * 4 + 1] = v.y;
        tile[k][nq * 4 + 2] = v.z; tile[k][nq * 4 + 3] = v.w;
    }
    __syncthreads();
    const int n  = tid >> 2;
    const int ko = (tid & 3) * 16;
    uint32_t hi[8], lo[8];
#pragma unroll
    for (int p = 0; p < 8; p++)
        split2(tile[ko + 2 * p][n], tile[ko + 2 * p + 1][n], hi[p], lo[p]);
    size_t dst = (size_t)(n0 + n) * F_ + k0 + ko;
    *reinterpret_cast<uint4*>(g_wh + dst)     = make_uint4(hi[0], hi[1], hi[2], hi[3]);
    *reinterpret_cast<uint4*>(g_wh + dst + 8) = make_uint4(hi[4], hi[5], hi[6], hi[7]);
    *reinterpret_cast<uint4*>(g_wl + dst)     = make_uint4(lo[0], lo[1], lo[2], lo[3]);
    *reinterpret_cast<uint4*>(g_wl + dst + 8) = make_uint4(lo[4], lo[5], lo[6], lo[7]);
}

// ---------------------------------------------------------------------------
// Kernel 1: mma.sync GEMM, 3-pass hi/lo, fragments via ldmatrix.x4.
// CTA tile 128x64, BK=32, grid (32,4), 256 threads = 8 warps (2m x 4n),
// warp tile m64 x n16. Double-buffered smem, one __syncthreads per k-tile.
// ---------------------------------------------------------------------------
#define AH_E  0
#define AL_E  (128 * PADK)
#define BH_E  (2 * 128 * PADK)
#define BL_E  (2 * 128 * PADK + 64 * PADK)
#define BUFE  (2 * 128 * PADK + 2 * 64 * PADK)      // 15360 bf16 = 30720 B
#define GEMM_SMEM (2 * BUFE * 2)                    // 61440 B

__global__ __launch_bounds__(256, 1)
void gate_gemm_mma(const float* __restrict__ bl) {
    extern __shared__ __nv_bfloat16 sm[];

    const int tid  = threadIdx.x;
    const int warp = tid >> 5;
    const int lane = tid & 31;
    const int wm   = (warp >> 2) * 64;      // 0 or 64
    const int wn   = (warp & 3) * 16;       // 0,16,32,48
    const int g    = lane >> 2;
    const int tq   = lane & 3;
    const int m0   = blockIdx.x * 128;
    const int n0   = blockIdx.y * 64;

    // ldmatrix per-lane source rows (element offsets into a buffer)
    const int arow = wm + (lane & 15);
    const int akh  = ((lane >> 4) & 1) * 8;               // A k-half
    const int brow = wn + (lane & 7) + ((lane >> 4) & 1) * 8;
    const int bkh  = ((lane >> 3) & 1) * 8;               // B k-half
    const uint32_t sb = smaddr(sm);
    const uint32_t aAh = sb + 2 * (AH_E + arow * PADK + akh);
    const uint32_t aAl = sb + 2 * (AL_E + arow * PADK + akh);
    const uint32_t aBh = sb + 2 * (BH_E + brow * PADK + bkh);
    const uint32_t aBl = sb + 2 * (BL_E + brow * PADK + bkh);

    // staging maps (LDG.128 -> STS.128 of pre-split data)
    const int srow = tid >> 2;              // 0..63
    const int sv   = tid & 3;               // 16B vec within 64B
    const uint4* pxh0 = reinterpret_cast<const uint4*>(g_xh + (size_t)(m0 + srow) * F_) + sv;
    const uint4* pxh1 = reinterpret_cast<const uint4*>(g_xh + (size_t)(m0 + 64 + srow) * F_) + sv;
    const uint4* pxl0 = reinterpret_cast<const uint4*>(g_xl + (size_t)(m0 + srow) * F_) + sv;
    const uint4* pxl1 = reinterpret_cast<const uint4*>(g_xl + (size_t)(m0 + 64 + srow) * F_) + sv;
    const uint4* pwh  = reinterpret_cast<const uint4*>(g_wh + (size_t)(n0 + srow) * F_) + sv;
    const uint4* pwl  = reinterpret_cast<const uint4*>(g_wl + (size_t)(n0 + srow) * F_) + sv;

    float acc[4][2][4];
#pragma unroll
    for (int mt = 0; mt < 4; mt++)
#pragma unroll
        for (int nt = 0; nt < 2; nt++)
#pragma unroll
            for (int r = 0; r < 4; r++) acc[mt][nt][r] = 0.f;

    uint4 rh0 = pxh0[0], rh1 = pxh1[0], rl0 = pxl0[0], rl1 = pxl1[0];
    uint4 rbh = pwh[0],  rbl = pwl[0];

    const int NKT = F_ / 32;
    for (int kt = 0; kt < NKT; kt++) {
        const int be = (kt & 1) * BUFE;
        __nv_bfloat16* buf = sm + be;
        *reinterpret_cast<uint4*>(buf + AH_E + (size_t)srow * PADK + sv * 8)        = rh0;
        *reinterpret_cast<uint4*>(buf + AH_E + (size_t)(64 + srow) * PADK + sv * 8) = rh1;
        *reinterpret_cast<uint4*>(buf + AL_E + (size_t)srow * PADK + sv * 8)        = rl0;
        *reinterpret_cast<uint4*>(buf + AL_E + (size_t)(64 + srow) * PADK + sv * 8) = rl1;
        *reinterpret_cast<uint4*>(buf + BH_E + (size_t)srow * PADK + sv * 8)        = rbh;
        *reinterpret_cast<uint4*>(buf + BL_E + (size_t)srow * PADK + sv * 8)        = rbl;
        __syncthreads();

        if (kt < NKT - 1) {                 // prefetch next k-tile
            int o = (kt + 1) * 4;
            rh0 = pxh0[o]; rh1 = pxh1[o]; rl0 = pxl0[o]; rl1 = pxl1[o];
            rbh = pwh[o];  rbl = pwl[o];
        }

        const uint32_t bofs = 2 * be;
#pragma unroll
        for (int ks = 0; ks < 32; ks += 16) {
            uint32_t bh[4], blo[4];
            ldsm4(bh,  aBh + bofs + 2 * ks);
            ldsm4(blo, aBl + bofs + 2 * ks);
#pragma unroll
            for (int mt = 0; mt < 4; mt++) {
                uint32_t ah[4], al[4];
                ldsm4(ah, aAh + bofs + 2 * (mt * 16 * PADK + ks));
                ldsm4(al, aAl + bofs + 2 * (mt * 16 * PADK + ks));
                mma_bf16(acc[mt][0], ah, bh[0],  bh[1]);
                mma_bf16(acc[mt][1], ah, bh[2],  bh[3]);
                mma_bf16(acc[mt][0], al, bh[0],  bh[1]);
                mma_bf16(acc[mt][1], al, bh[2],  bh[3]);
                mma_bf16(acc[mt][0], ah, blo[0], blo[1]);
                mma_bf16(acc[mt][1], ah, blo[2], blo[3]);
            }
        }
        // single barrier per iter is safe with double buffering (see R7 note)
    }

    // epilogue: bias + store (c0,c1 at row g, c2,c3 at g+8)
#pragma unroll
    for (int nt = 0; nt < 2; nt++) {
        int n = n0 + wn + nt * 8 + 2 * tq;
        float2 bias = *reinterpret_cast<const float2*>(&bl[n]);
#pragma unroll
        for (int mt = 0; mt < 4; mt++) {
            int m = m0 + wm + mt * 16 + g;
            float2 o0, o1;
            o0.x = acc[mt][nt][0] + bias.x;  o0.y = acc[mt][nt][1] + bias.y;
            o1.x = acc[mt][nt][2] + bias.x;  o1.y = acc[mt][nt][3] + bias.y;
            *reinterpret_cast<float2*>(&g_G[(size_t)m * G4 + n])       = o0;
            *reinterpret_cast<float2*>(&g_G[(size_t)(m + 8) * G4 + n]) = o1;
        }
    }
}

// ---------------------------------------------------------------------------
// Kernel 2: LSTM recurrence. 1 CTA/batch, 256 threads = 8 warps.
// Lane l of warp w: dot for (gate = l>>3, unit = 8w + (l&7)).
// G slice staged in smem (32KB, no spills, no in-loop LDG). Each lane applies
// its OWN gate's nonlinearity (1 ex2 + 1 rcp), THEN shuffles activated values
// -> 4 MUFU/warp/step instead of 10. One __syncthreads per step.
// ---------------------------------------------------------------------------
__device__ __forceinline__ unsigned long long pk2(float lo, float hi) {
    unsigned long long r;
    asm("mov.b64 %0, {%1, %2};" : "=l"(r) : "f"(lo), "f"(hi));
    return r;
}
__device__ __forceinline__ unsigned long long fma2_(unsigned long long a,
                                                    unsigned long long b,
                                                    unsigned long long c) {
    unsigned long long d;
    asm("fma.rn.f32x2 %0, %1, %2, %3;" : "=l"(d) : "l"(a), "l"(b), "l"(c));
    return d;
}
__device__ __forceinline__ void upk2(float& lo, float& hi, unsigned long long v) {
    asm("mov.b64 {%0, %1}, %2;" : "=f"(lo), "=f"(hi) : "l"(v));
}

__global__ __launch_bounds__(256, 1)
void lstm_rec(const float* __restrict__ Wh, float* __restrict__ out) {
    const int b   = blockIdx.x;
    const int tid = threadIdx.x;
    const int w   = tid >> 5;
    const int l   = tid & 31;
    const int u   = 8 * w + (l & 7);
    const int gq  = l >> 3;
    const int n   = gq * 64 + u;

    __shared__ __align__(16) float Gsh[W_ * G4];     // 32 KB
    __shared__ __align__(16) float hbuf[2][H_];

    // activation params: gate 2 (g~) is tanh, others sigmoid.
    //   y = 1/(1 + e^{a*v});  res = fb*y + fc
    const float fa = (gq == 2) ? -2.0f : -1.0f;
    const float fb = (gq == 2) ?  2.0f :  1.0f;
    const float fc = (gq == 2) ? -1.0f :  0.0f;

    // Wh[:, n] packed along k (64 weights -> 32 f32x2)
    unsigned long long wh2[32];
#pragma unroll
    for (int kk = 0; kk < 32; kk++)
        wh2[kk] = pk2(Wh[(2 * kk) * G4 + n], Wh[(2 * kk + 1) * G4 + n]);

    // stage this batch's G slice into smem (coalesced LDG.128 -> STS.128)
    {
        const float4* src = reinterpret_cast<const float4*>(g_G + (size_t)b * W_ * G4);
        float4* dst = reinterpret_cast<float4*>(Gsh);
#pragma unroll
        for (int j = 0; j < 8; j++) dst[j * 256 + tid] = src[j * 256 + tid];
    }
    if (tid < H_) hbuf[0][tid] = 0.0f;
    float c = 0.0f;
    __syncthreads();

    int p = 0;
    for (int t = 0; t < W_; t++) {
        const unsigned long long* h2 =
            reinterpret_cast<const unsigned long long*>(hbuf[p]);

        unsigned long long a0 = pk2(Gsh[t * G4 + n], 0.0f);
        unsigned long long a1 = 0ull, a2 = 0ull, a3 = 0ull;
#pragma unroll
        for (int kk = 0; kk < 8; kk++) {
            a0 = fma2_(h2[kk],      wh2[kk],      a0);
            a1 = fma2_(h2[8 + kk],  wh2[8 + kk],  a1);
            a2 = fma2_(h2[16 + kk], wh2[16 + kk], a2);
            a3 = fma2_(h2[24 + kk], wh2[24 + kk], a3);
        }
        float s0, s1, s2, s3, s4, s5, s6, s7;
        upk2(s0, s1, a0); upk2(s2, s3, a1);
        upk2(s4, s5, a2); upk2(s6, s7, a3);
        float v = ((s0 + s1) + (s2 + s3)) + ((s4 + s5) + (s6 + s7));

        // per-lane activation of OWN gate (saturates correctly at +-inf)
        float y   = 1.0f / (1.0f + __expf(fa * v));
        float act = fmaf(fb, y, fc);

        // gather activated gates for unit (l&7) from lanes {0,8,16,24}+(l&7)
        int src = l & 7;
        float ig = __shfl_sync(0xFFFFFFFFu, act, src);
        float fg = __shfl_sync(0xFFFFFFFFu, act, src + 8);
        float gg = __shfl_sync(0xFFFFFFFFu, act, src + 16);
        float og = __shfl_sync(0xFFFFFFFFu, act, src + 24);

        c = fg * c + ig * gg;
        float tc = fmaf(2.0f, 1.0f / (1.0f + __expf(-2.0f * c)), -1.0f);  // tanh(c)
        float hn = og * tc;
        if (l < 8) {
            out[(size_t)b * (W_ * H_) + t * H_ + u] = c;   // output = cell state
            hbuf[p ^ 1][u] = hn;
        }
        p ^= 1;
        __syncthreads();
    }
}

// ---------------------------------------------------------------------------
// Launch
// ---------------------------------------------------------------------------
extern "C" void kernel_launch(void* const* d_in, const int* in_sizes, int n_in,
                              void* d_out, int out_size) {
    const float* x   = (const float*)d_in[0];   // [B, F, W]
    // d_in[1..5] (attention params) are dead: softmax over size-1 axis == 1.
    const float* Wx  = (const float*)d_in[6];   // [F, 4H]
    const float* Wh  = (const float*)d_in[7];   // [H, 4H]
    const float* blm = (const float*)d_in[8];   // [4H]
    float* out = (float*)d_out;                 // [B, W, H]

    cudaFuncSetAttribute(gate_gemm_mma,
                         cudaFuncAttributeMaxDynamicSharedMemorySize, GEMM_SMEM);

    split_x<<<dim3(8, 128), 256>>>(x);
    split_w<<<dim3(16, 4), 256>>>(Wx);
    gate_gemm_mma<<<dim3(32, 4), 256, GEMM_SMEM>>>(blm);
    lstm_rec<<<B_, 256>>>(Wh, out);
}